// round 7
// baseline (speedup 1.0000x reference)
#include <cuda_runtime.h>
#include <cuda_fp16.h>

#define NN 50000
#define EE 800000
#define CC 64
#define BN_EPS 1e-5f

// ---------------- packed f32x2 helpers (Blackwell sm_103a) -------------------
#define PACK_DUP2(out, f) \
    asm("mov.b64 %0, {%1, %1};" : "=l"(out) : "r"(__float_as_uint(f)))
#define PACK2(out, f0, f1) \
    asm("mov.b64 %0, {%1, %2};" : "=l"(out) : "r"(__float_as_uint(f0)), "r"(__float_as_uint(f1)))
#define FMA2(d, a, b) \
    asm("fma.rn.f32x2 %0, %1, %2, %0;" : "+l"(d) : "l"(a), "l"(b))
#define UNPACK2(lo, hi, v) \
    asm("mov.b64 {%0, %1}, %2;" : "=r"(lo), "=r"(hi) : "l"(v))

// ---------------- scratch (static device arrays; no allocation) -------------
__device__ float2   g_cs[NN];        // (sum s, sum s^2) per src node
__device__ float    g_S1[CC];
__device__ float    g_S2[CC];
__device__ float    g_hsum[CC];
__device__ float    g_hsq[CC];
__device__ __half2  g_Yh[NN * 32];   // X @ pool_W, fp16x2 (k4 gather only)
__device__ float    g_aggf[NN * CC]; // scatter-max result (>= 0)

// ---------------- K0: zero small per-replay state -----------------------------
__global__ void k0_zero() {
    int i = blockIdx.x * blockDim.x + threadIdx.x;
    if (i < NN) g_cs[i] = make_float2(0.f, 0.f);
    if (i < CC) { g_S1[i] = 0.f; g_S2[i] = 0.f; g_hsum[i] = 0.f; g_hsq[i] = 0.f; }
}

// ---------------- K1: per-src sums of s, s^2 + zero agg ------------------------
__global__ void k1_edge_stats(const int* __restrict__ ei,
                              const float* __restrict__ ew,
                              const float* __restrict__ coefp) {
    int i = blockIdx.x * blockDim.x + threadIdx.x;
    int stride = gridDim.x * blockDim.x;
    // zero scatter-max target (safe: k1 atomics touch only g_cs; k4 runs later)
    float4 z = make_float4(0.f, 0.f, 0.f, 0.f);
    float4* a4 = reinterpret_cast<float4*>(g_aggf);
    for (int idx = i; idx < NN * CC / 4; idx += stride) a4[idx] = z;
    if (i >= EE) return;
    float coef = __ldg(coefp);
    int src = ei[i];
    float s = fmaf(coef, ew[i], 1.0f);
    atomicAdd(&g_cs[src].x, s);
    atomicAdd(&g_cs[src].y, s * s);
}

// ---------------- K2: Y = X @ pool_W (f32x2) + fused BN-stats, fp16 Y out -----
// 64 threads (2 warps). Warp w = column-half w of rows [b*128 + lane + 32j].
__global__ void __launch_bounds__(64) k2_xw(const float* __restrict__ x,
                                            const float* __restrict__ W) {
    __shared__ float Ws[CC * CC];   // 16 KB; reused as reduction buffer
    for (int i = threadIdx.x; i < CC * CC; i += 64) Ws[i] = W[i];
    __syncthreads();
    int half = threadIdx.x >> 5;
    int lane = threadIdx.x & 31;
    int rbase = blockIdx.x * 128 + lane;
    int r[4]; bool ok[4];
#pragma unroll
    for (int j = 0; j < 4; j++) { r[j] = rbase + 32 * j; ok[j] = r[j] < NN; }

    unsigned long long acc[4][16];
#pragma unroll
    for (int j = 0; j < 4; j++)
#pragma unroll
        for (int p = 0; p < 16; p++) acc[j][p] = 0ull;

    const float4 z4 = make_float4(0.f, 0.f, 0.f, 0.f);
#pragma unroll 4
    for (int k4 = 0; k4 < 16; k4++) {
        float4 xv[4];
#pragma unroll
        for (int j = 0; j < 4; j++)
            xv[j] = ok[j] ? *reinterpret_cast<const float4*>(
                                x + (size_t)r[j] * CC + k4 * 4)
                          : z4;
        float xk[4][4];
#pragma unroll
        for (int j = 0; j < 4; j++) {
            xk[j][0] = xv[j].x; xk[j][1] = xv[j].y;
            xk[j][2] = xv[j].z; xk[j][3] = xv[j].w;
        }
#pragma unroll
        for (int kk = 0; kk < 4; kk++) {
            unsigned long long a[4];
#pragma unroll
            for (int j = 0; j < 4; j++) PACK_DUP2(a[j], xk[j][kk]);
            const ulonglong2* wr = reinterpret_cast<const ulonglong2*>(
                &Ws[(k4 * 4 + kk) * CC + half * 32]);
#pragma unroll
            for (int p = 0; p < 8; p++) {
                ulonglong2 w = wr[p];
#pragma unroll
                for (int j = 0; j < 4; j++) {
                    FMA2(acc[j][2 * p],     a[j], w.x);
                    FMA2(acc[j][2 * p + 1], a[j], w.y);
                }
            }
        }
    }

    // epilogue: store Y (fp16) and accumulate BN-stat partials (fp32)
    float2 cs[4];
#pragma unroll
    for (int j = 0; j < 4; j++)
        cs[j] = ok[j] ? g_cs[r[j]] : make_float2(0.f, 0.f);
    float p1[32], p2[32];
#pragma unroll
    for (int c = 0; c < 32; c++) { p1[c] = 0.f; p2[c] = 0.f; }
#pragma unroll
    for (int j = 0; j < 4; j++) {
        float yv[32];
#pragma unroll
        for (int p = 0; p < 16; p++) {
            unsigned u0, u1;
            UNPACK2(u0, u1, acc[j][p]);
            yv[2 * p]     = __uint_as_float(u0);
            yv[2 * p + 1] = __uint_as_float(u1);
        }
        if (ok[j]) {
            __half2 hh[16];
#pragma unroll
            for (int c2 = 0; c2 < 16; c2++)
                hh[c2] = __floats2half2_rn(yv[2 * c2], yv[2 * c2 + 1]);
            uint4* dst = reinterpret_cast<uint4*>(g_Yh + (size_t)r[j] * 32 + half * 16);
            const uint4* srcv = reinterpret_cast<const uint4*>(hh);
#pragma unroll
            for (int q = 0; q < 4; q++) dst[q] = srcv[q];
        }
#pragma unroll
        for (int c = 0; c < 32; c++) {
            p1[c] += cs[j].x * yv[c];
            p2[c] += cs[j].y * yv[c] * yv[c];
        }
    }
    // block reduction through smem (Ws is dead now)
    __syncthreads();
    float* red = Ws + half * 2048;   // per-warp region: 32 lanes x 64 floats
#pragma unroll
    for (int c = 0; c < 32; c++) {
        red[lane * 64 + c]      = p1[c];
        red[lane * 64 + 32 + c] = p2[c];
    }
    __syncwarp();
    float a = 0.f, b = 0.f;
#pragma unroll
    for (int k = 0; k < 32; k++) {
        a += red[k * 64 + lane];
        b += red[k * 64 + 32 + lane];
    }
    atomicAdd(&g_S1[half * 32 + lane], a);
    atomicAdd(&g_S2[half * 32 + lane], b);
}

// ---------------- K4: filtered scatter-max, 2 edges per warp-iteration --------
// Half-warp (16 lanes) per edge, 4 channels per lane. EE % 32 == 0, so no
// boundary logic. Filter: plain-load current agg, atomicMax only if greater
// (safe: agg is monotone non-decreasing from 0).
__global__ void __launch_bounds__(256) k4_scatter(const int* __restrict__ ei,
                                                  const float* __restrict__ ew,
                                                  const float* __restrict__ coefp,
                                                  const float* __restrict__ pb,
                                                  const float* __restrict__ gamma,
                                                  const float* __restrict__ beta) {
    __shared__ float s_al[CC], s_de[CC];
    if (threadIdx.x < CC) {
        int c = threadIdx.x;
        float invE = 1.0f / (float)EE;
        float bb = pb[c];
        float mean = g_S1[c] * invE + bb;
        float msq = (g_S2[c] + 2.f * bb * g_S1[c]) * invE + bb * bb;
        float var = msq - mean * mean;
        float alpha = gamma[c] * rsqrtf(var + BN_EPS);
        s_al[c] = alpha;
        s_de[c] = beta[c] + alpha * (bb - mean);
    }
    __syncthreads();
    float coef = __ldg(coefp);
    int lane = threadIdx.x & 31;
    int sub  = lane & 15;        // sublane within half-warp
    int hw   = lane >> 4;        // which edge of the pair
    float al[4], de[4];
#pragma unroll
    for (int q = 0; q < 4; q++) { al[q] = s_al[4 * sub + q]; de[q] = s_de[4 * sub + q]; }
    int warp = (blockIdx.x * blockDim.x + threadIdx.x) >> 5;
    int nwarps = (gridDim.x * blockDim.x) >> 5;
    for (int base = warp * 32; base < EE; base += nwarps * 32) {
        int e = base + lane;
        int src = ei[e];
        int dst = ei[EE + e];
        float s = fmaf(coef, ew[e], 1.0f);
#pragma unroll 4
        for (int i = 0; i < 32; i += 2) {
            int idx = i + hw;    // per-lane source slot
            int   sI = __shfl_sync(0xffffffffu, src, idx);
            int   dI = __shfl_sync(0xffffffffu, dst, idx);
            float sS = __shfl_sync(0xffffffffu, s, idx);
            uint2 yu = __ldg(reinterpret_cast<const uint2*>(
                g_Yh + (size_t)sI * 32) + sub);
            float2 y01 = __half22float2(*reinterpret_cast<__half2*>(&yu.x));
            float2 y23 = __half22float2(*reinterpret_cast<__half2*>(&yu.y));
            float* arow = g_aggf + (size_t)dI * CC + 4 * sub;
            float4 cur = *reinterpret_cast<const float4*>(arow);
            float v0 = fmaf(al[0] * sS, y01.x, de[0]);
            float v1 = fmaf(al[1] * sS, y01.y, de[1]);
            float v2 = fmaf(al[2] * sS, y23.x, de[2]);
            float v3 = fmaf(al[3] * sS, y23.y, de[3]);
            unsigned* au = reinterpret_cast<unsigned*>(arow);
            if (v0 > cur.x) atomicMax(au,     __float_as_uint(v0));
            if (v1 > cur.y) atomicMax(au + 1, __float_as_uint(v1));
            if (v2 > cur.z) atomicMax(au + 2, __float_as_uint(v2));
            if (v3 > cur.w) atomicMax(au + 3, __float_as_uint(v3));
        }
    }
}

// ---------------- K5: h = [x, agg] @ final_W + b (f32x2) + fused h-stats -------
__global__ void __launch_bounds__(64) k5_final(const float* __restrict__ x,
                                               const float* __restrict__ Wf,
                                               const float* __restrict__ fb,
                                               float* __restrict__ hout) {
    __shared__ float Ws[2 * CC * CC];   // 32 KB; front 16 KB reused for reduction
    for (int i = threadIdx.x; i < 2 * CC * CC; i += 64) Ws[i] = Wf[i];
    __syncthreads();
    int half = threadIdx.x >> 5;
    int lane = threadIdx.x & 31;
    int rbase = blockIdx.x * 128 + lane;
    int r[4]; bool ok[4];
#pragma unroll
    for (int j = 0; j < 4; j++) { r[j] = rbase + 32 * j; ok[j] = r[j] < NN; }

    unsigned long long acc[4][16];
    {
        const float* fbh = fb + half * 32;
        unsigned long long binit[16];
#pragma unroll
        for (int p = 0; p < 16; p++) PACK2(binit[p], fbh[2 * p], fbh[2 * p + 1]);
#pragma unroll
        for (int j = 0; j < 4; j++)
#pragma unroll
            for (int p = 0; p < 16; p++) acc[j][p] = binit[p];
    }

    const float4 z4 = make_float4(0.f, 0.f, 0.f, 0.f);
#pragma unroll
    for (int ph = 0; ph < 2; ph++) {
        const float* src = (ph == 0) ? x : g_aggf;
        const float* Wb  = Ws + ph * CC * CC;
#pragma unroll 4
        for (int k4 = 0; k4 < 16; k4++) {
            float4 xv[4];
#pragma unroll
            for (int j = 0; j < 4; j++)
                xv[j] = ok[j] ? *reinterpret_cast<const float4*>(
                                    src + (size_t)r[j] * CC + k4 * 4)
                              : z4;
            float xk[4][4];
#pragma unroll
            for (int j = 0; j < 4; j++) {
                xk[j][0] = xv[j].x; xk[j][1] = xv[j].y;
                xk[j][2] = xv[j].z; xk[j][3] = xv[j].w;
            }
#pragma unroll
            for (int kk = 0; kk < 4; kk++) {
                unsigned long long a[4];
#pragma unroll
                for (int j = 0; j < 4; j++) PACK_DUP2(a[j], xk[j][kk]);
                const ulonglong2* wr = reinterpret_cast<const ulonglong2*>(
                    &Wb[(k4 * 4 + kk) * CC + half * 32]);
#pragma unroll
                for (int p = 0; p < 8; p++) {
                    ulonglong2 w = wr[p];
#pragma unroll
                    for (int j = 0; j < 4; j++) {
                        FMA2(acc[j][2 * p],     a[j], w.x);
                        FMA2(acc[j][2 * p + 1], a[j], w.y);
                    }
                }
            }
        }
    }

    // epilogue: store h + accumulate per-channel sum / sumsq
    float p1[32], p2[32];
#pragma unroll
    for (int c = 0; c < 32; c++) { p1[c] = 0.f; p2[c] = 0.f; }
#pragma unroll
    for (int j = 0; j < 4; j++) {
        float hv[32];
#pragma unroll
        for (int p = 0; p < 16; p++) {
            unsigned u0, u1;
            UNPACK2(u0, u1, acc[j][p]);
            hv[2 * p]     = __uint_as_float(u0);
            hv[2 * p + 1] = __uint_as_float(u1);
        }
        if (ok[j]) {
            float* dst = hout + (size_t)r[j] * CC + half * 32;
#pragma unroll
            for (int q = 0; q < 8; q++) {
                float4 v;
                v.x = hv[4 * q]; v.y = hv[4 * q + 1];
                v.z = hv[4 * q + 2]; v.w = hv[4 * q + 3];
                *reinterpret_cast<float4*>(dst + q * 4) = v;
            }
#pragma unroll
            for (int c = 0; c < 32; c++) {
                p1[c] += hv[c];
                p2[c] += hv[c] * hv[c];
            }
        }
    }
    __syncthreads();
    float* red = Ws + half * 2048;
#pragma unroll
    for (int c = 0; c < 32; c++) {
        red[lane * 64 + c]      = p1[c];
        red[lane * 64 + 32 + c] = p2[c];
    }
    __syncwarp();
    float a = 0.f, b = 0.f;
#pragma unroll
    for (int k = 0; k < 32; k++) {
        a += red[k * 64 + lane];
        b += red[k * 64 + 32 + lane];
    }
    atomicAdd(&g_hsum[half * 32 + lane], a);
    atomicAdd(&g_hsq[half * 32 + lane], b);
}

// ---------------- K7: out = relu(a2*out + b2), in place (BN coeffs fused) ------
__global__ void __launch_bounds__(256) k7_epilogue(float* __restrict__ out,
                                                   const float* __restrict__ gamma,
                                                   const float* __restrict__ beta) {
    __shared__ float s_a[CC], s_b[CC];
    if (threadIdx.x < CC) {
        int c = threadIdx.x;
        float invN = 1.0f / (float)NN;
        float mean = g_hsum[c] * invN;
        float var = g_hsq[c] * invN - mean * mean;
        float a = gamma[c] * rsqrtf(var + BN_EPS);
        s_a[c] = a;
        s_b[c] = beta[c] - a * mean;
    }
    __syncthreads();
    int i = blockIdx.x * blockDim.x + threadIdx.x;
    int stride = gridDim.x * blockDim.x;
    float4* ov = reinterpret_cast<float4*>(out);
    for (int q = i; q < NN * 16; q += stride) {
        int c4 = (q & 15) * 4;
        float4 h = ov[q];
        float4 r;
        r.x = fmaxf(0.f, fmaf(s_a[c4 + 0], h.x, s_b[c4 + 0]));
        r.y = fmaxf(0.f, fmaf(s_a[c4 + 1], h.y, s_b[c4 + 1]));
        r.z = fmaxf(0.f, fmaf(s_a[c4 + 2], h.z, s_b[c4 + 2]));
        r.w = fmaxf(0.f, fmaf(s_a[c4 + 3], h.w, s_b[c4 + 3]));
        ov[q] = r;
    }
}

// ---------------- launch ---------------------------------------------------------
extern "C" void kernel_launch(void* const* d_in, const int* in_sizes, int n_in,
                              void* d_out, int out_size) {
    const float* x     = (const float*)d_in[0];
    const int*   ei    = (const int*)d_in[1];
    const float* ew    = (const float*)d_in[2];
    const float* pW    = (const float*)d_in[3];
    const float* pb    = (const float*)d_in[4];
    const float* pg    = (const float*)d_in[5];
    const float* pbeta = (const float*)d_in[6];
    const float* fW    = (const float*)d_in[7];
    const float* fb    = (const float*)d_in[8];
    const float* fg    = (const float*)d_in[9];
    const float* fbeta = (const float*)d_in[10];
    const float* coef  = (const float*)d_in[11];
    float* out = (float*)d_out;

    const int rowBlocks = (NN + 127) / 128;   // 391
    k0_zero<<<(NN + 255) / 256, 256>>>();
    k1_edge_stats<<<(EE + 255) / 256, 256>>>(ei, ew, coef);
    k2_xw<<<rowBlocks, 64>>>(x, pW);
    k4_scatter<<<1184, 256>>>(ei, ew, coef, pb, pg, pbeta);
    k5_final<<<rowBlocks, 64>>>(x, fW, fb, out);
    k7_epilogue<<<1024, 256>>>(out, fg, fbeta);
}

// round 8
// speedup vs baseline: 1.0620x; 1.0620x over previous
#include <cuda_runtime.h>
#include <cuda_fp16.h>

#define NN 50000
#define EE 800000
#define CC 64
#define BN_EPS 1e-5f

// ---------------- packed f32x2 helpers (Blackwell sm_103a) -------------------
#define PACK_DUP2(out, f) \
    asm("mov.b64 %0, {%1, %1};" : "=l"(out) : "r"(__float_as_uint(f)))
#define PACK2(out, f0, f1) \
    asm("mov.b64 %0, {%1, %2};" : "=l"(out) : "r"(__float_as_uint(f0)), "r"(__float_as_uint(f1)))
#define FMA2(d, a, b) \
    asm("fma.rn.f32x2 %0, %1, %2, %0;" : "+l"(d) : "l"(a), "l"(b))
#define UNPACK2(lo, hi, v) \
    asm("mov.b64 {%0, %1}, %2;" : "=r"(lo), "=r"(hi) : "l"(v))

// ---------------- scratch (static device arrays; no allocation) -------------
__device__ float2   g_cs[NN];        // (sum s, sum s^2) per src node
__device__ float    g_S1[CC];
__device__ float    g_S2[CC];
__device__ float    g_hsum[CC];
__device__ float    g_hsq[CC];
__device__ __half2  g_Yh[NN * 32];   // X @ pool_W, fp16x2 (k4 gather only)
__device__ float    g_aggf[NN * CC]; // scatter-max result (>= 0)

// ---------------- K0: zero small per-replay state -----------------------------
__global__ void k0_zero() {
    int i = blockIdx.x * blockDim.x + threadIdx.x;
    if (i < NN) g_cs[i] = make_float2(0.f, 0.f);
    if (i < CC) { g_S1[i] = 0.f; g_S2[i] = 0.f; g_hsum[i] = 0.f; g_hsq[i] = 0.f; }
}

// ---------------- K1: per-src sums of s, s^2 + zero agg ------------------------
__global__ void k1_edge_stats(const int* __restrict__ ei,
                              const float* __restrict__ ew,
                              const float* __restrict__ coefp) {
    int i = blockIdx.x * blockDim.x + threadIdx.x;
    int stride = gridDim.x * blockDim.x;
    // zero scatter-max target (safe: k1 atomics touch only g_cs; k4 runs later)
    float4 z = make_float4(0.f, 0.f, 0.f, 0.f);
    float4* a4 = reinterpret_cast<float4*>(g_aggf);
    for (int idx = i; idx < NN * CC / 4; idx += stride) a4[idx] = z;
    if (i >= EE) return;
    float coef = __ldg(coefp);
    int src = ei[i];
    float s = fmaf(coef, ew[i], 1.0f);
    atomicAdd(&g_cs[src].x, s);
    atomicAdd(&g_cs[src].y, s * s);
}

// ---------------- K2: Y = X @ pool_W (f32x2) + fused BN-stats, fp16 Y out -----
// 64 threads (2 warps). Warp w = column-half w of rows [b*128 + lane + 32j].
__global__ void __launch_bounds__(64) k2_xw(const float* __restrict__ x,
                                            const float* __restrict__ W) {
    __shared__ float Ws[CC * CC];   // 16 KB; reused as reduction buffer
    for (int i = threadIdx.x; i < CC * CC; i += 64) Ws[i] = W[i];
    __syncthreads();
    int half = threadIdx.x >> 5;
    int lane = threadIdx.x & 31;
    int rbase = blockIdx.x * 128 + lane;
    int r[4]; bool ok[4];
#pragma unroll
    for (int j = 0; j < 4; j++) { r[j] = rbase + 32 * j; ok[j] = r[j] < NN; }

    unsigned long long acc[4][16];
#pragma unroll
    for (int j = 0; j < 4; j++)
#pragma unroll
        for (int p = 0; p < 16; p++) acc[j][p] = 0ull;

    const float4 z4 = make_float4(0.f, 0.f, 0.f, 0.f);
#pragma unroll 4
    for (int k4 = 0; k4 < 16; k4++) {
        float4 xv[4];
#pragma unroll
        for (int j = 0; j < 4; j++)
            xv[j] = ok[j] ? *reinterpret_cast<const float4*>(
                                x + (size_t)r[j] * CC + k4 * 4)
                          : z4;
        float xk[4][4];
#pragma unroll
        for (int j = 0; j < 4; j++) {
            xk[j][0] = xv[j].x; xk[j][1] = xv[j].y;
            xk[j][2] = xv[j].z; xk[j][3] = xv[j].w;
        }
#pragma unroll
        for (int kk = 0; kk < 4; kk++) {
            unsigned long long a[4];
#pragma unroll
            for (int j = 0; j < 4; j++) PACK_DUP2(a[j], xk[j][kk]);
            const ulonglong2* wr = reinterpret_cast<const ulonglong2*>(
                &Ws[(k4 * 4 + kk) * CC + half * 32]);
#pragma unroll
            for (int p = 0; p < 8; p++) {
                ulonglong2 w = wr[p];
#pragma unroll
                for (int j = 0; j < 4; j++) {
                    FMA2(acc[j][2 * p],     a[j], w.x);
                    FMA2(acc[j][2 * p + 1], a[j], w.y);
                }
            }
        }
    }

    // epilogue: store Y (fp16) and accumulate BN-stat partials (fp32)
    float2 cs[4];
#pragma unroll
    for (int j = 0; j < 4; j++)
        cs[j] = ok[j] ? g_cs[r[j]] : make_float2(0.f, 0.f);
    float p1[32], p2[32];
#pragma unroll
    for (int c = 0; c < 32; c++) { p1[c] = 0.f; p2[c] = 0.f; }
#pragma unroll
    for (int j = 0; j < 4; j++) {
        float yv[32];
#pragma unroll
        for (int p = 0; p < 16; p++) {
            unsigned u0, u1;
            UNPACK2(u0, u1, acc[j][p]);
            yv[2 * p]     = __uint_as_float(u0);
            yv[2 * p + 1] = __uint_as_float(u1);
        }
        if (ok[j]) {
            __half2 hh[16];
#pragma unroll
            for (int c2 = 0; c2 < 16; c2++)
                hh[c2] = __floats2half2_rn(yv[2 * c2], yv[2 * c2 + 1]);
            uint4* dst = reinterpret_cast<uint4*>(g_Yh + (size_t)r[j] * 32 + half * 16);
            const uint4* srcv = reinterpret_cast<const uint4*>(hh);
#pragma unroll
            for (int q = 0; q < 4; q++) dst[q] = srcv[q];
        }
#pragma unroll
        for (int c = 0; c < 32; c++) {
            p1[c] += cs[j].x * yv[c];
            p2[c] += cs[j].y * yv[c] * yv[c];
        }
    }
    // block reduction through smem (Ws is dead now)
    __syncthreads();
    float* red = Ws + half * 2048;   // per-warp region: 32 lanes x 64 floats
#pragma unroll
    for (int c = 0; c < 32; c++) {
        red[lane * 64 + c]      = p1[c];
        red[lane * 64 + 32 + c] = p2[c];
    }
    __syncwarp();
    float a = 0.f, b = 0.f;
#pragma unroll
    for (int k = 0; k < 32; k++) {
        a += red[k * 64 + lane];
        b += red[k * 64 + 32 + lane];
    }
    atomicAdd(&g_S1[half * 32 + lane], a);
    atomicAdd(&g_S2[half * 32 + lane], b);
}

// ---------------- K4: filtered scatter-max (round-6 layout, fewer MIO ops) ----
// Warp per edge, 2 channels/lane. src/dst packed into one shuffle word
// (both < 2^16). Filter: plain-load current agg, atomicMax only if greater
// (safe: agg is monotone non-decreasing from 0).
__global__ void __launch_bounds__(256) k4_scatter(const int* __restrict__ ei,
                                                  const float* __restrict__ ew,
                                                  const float* __restrict__ coefp,
                                                  const float* __restrict__ pb,
                                                  const float* __restrict__ gamma,
                                                  const float* __restrict__ beta) {
    __shared__ float s_al[CC], s_de[CC];
    if (threadIdx.x < CC) {
        int c = threadIdx.x;
        float invE = 1.0f / (float)EE;
        float bb = pb[c];
        float mean = g_S1[c] * invE + bb;
        float msq = (g_S2[c] + 2.f * bb * g_S1[c]) * invE + bb * bb;
        float var = msq - mean * mean;
        float alpha = gamma[c] * rsqrtf(var + BN_EPS);
        s_al[c] = alpha;
        s_de[c] = beta[c] + alpha * (bb - mean);
    }
    __syncthreads();
    float coef = __ldg(coefp);
    int lane = threadIdx.x & 31;
    int warp = (blockIdx.x * blockDim.x + threadIdx.x) >> 5;
    int nwarps = (gridDim.x * blockDim.x) >> 5;
    float al0 = s_al[2 * lane], al1 = s_al[2 * lane + 1];
    float de0 = s_de[2 * lane], de1 = s_de[2 * lane + 1];
    for (int base = warp * 32; base < EE; base += nwarps * 32) {
        int e = base + lane;
        unsigned pk = (unsigned)ei[e] | ((unsigned)ei[EE + e] << 16);
        float s = fmaf(coef, ew[e], 1.0f);
#pragma unroll 8
        for (int i = 0; i < 32; i++) {
            unsigned pkI = __shfl_sync(0xffffffffu, pk, i);
            float    sS  = __shfl_sync(0xffffffffu, s, i);
            unsigned sI = pkI & 0xffffu;
            unsigned dI = pkI >> 16;
            __half2 yh = __ldg(g_Yh + (size_t)sI * 32 + lane);
            float2 yv = __half22float2(yh);
            float v0 = fmaf(al0 * sS, yv.x, de0);
            float v1 = fmaf(al1 * sS, yv.y, de1);
            float* arow = g_aggf + (size_t)dI * CC + 2 * lane;
            float2 cur = *reinterpret_cast<const float2*>(arow);
            unsigned* au = reinterpret_cast<unsigned*>(arow);
            if (v0 > cur.x) atomicMax(au,     __float_as_uint(v0));
            if (v1 > cur.y) atomicMax(au + 1, __float_as_uint(v1));
        }
    }
}

// ---------------- K5: h = [x, agg] @ final_W + b (f32x2) + fused h-stats -------
__global__ void __launch_bounds__(64) k5_final(const float* __restrict__ x,
                                               const float* __restrict__ Wf,
                                               const float* __restrict__ fb,
                                               float* __restrict__ hout) {
    __shared__ float Ws[2 * CC * CC];   // 32 KB; front 16 KB reused for reduction
    for (int i = threadIdx.x; i < 2 * CC * CC; i += 64) Ws[i] = Wf[i];
    __syncthreads();
    int half = threadIdx.x >> 5;
    int lane = threadIdx.x & 31;
    int rbase = blockIdx.x * 128 + lane;
    int r[4]; bool ok[4];
#pragma unroll
    for (int j = 0; j < 4; j++) { r[j] = rbase + 32 * j; ok[j] = r[j] < NN; }

    unsigned long long acc[4][16];
    {
        const float* fbh = fb + half * 32;
        unsigned long long binit[16];
#pragma unroll
        for (int p = 0; p < 16; p++) PACK2(binit[p], fbh[2 * p], fbh[2 * p + 1]);
#pragma unroll
        for (int j = 0; j < 4; j++)
#pragma unroll
            for (int p = 0; p < 16; p++) acc[j][p] = binit[p];
    }

    const float4 z4 = make_float4(0.f, 0.f, 0.f, 0.f);
#pragma unroll
    for (int ph = 0; ph < 2; ph++) {
        const float* src = (ph == 0) ? x : g_aggf;
        const float* Wb  = Ws + ph * CC * CC;
#pragma unroll 4
        for (int k4 = 0; k4 < 16; k4++) {
            float4 xv[4];
#pragma unroll
            for (int j = 0; j < 4; j++)
                xv[j] = ok[j] ? *reinterpret_cast<const float4*>(
                                    src + (size_t)r[j] * CC + k4 * 4)
                              : z4;
            float xk[4][4];
#pragma unroll
            for (int j = 0; j < 4; j++) {
                xk[j][0] = xv[j].x; xk[j][1] = xv[j].y;
                xk[j][2] = xv[j].z; xk[j][3] = xv[j].w;
            }
#pragma unroll
            for (int kk = 0; kk < 4; kk++) {
                unsigned long long a[4];
#pragma unroll
                for (int j = 0; j < 4; j++) PACK_DUP2(a[j], xk[j][kk]);
                const ulonglong2* wr = reinterpret_cast<const ulonglong2*>(
                    &Wb[(k4 * 4 + kk) * CC + half * 32]);
#pragma unroll
                for (int p = 0; p < 8; p++) {
                    ulonglong2 w = wr[p];
#pragma unroll
                    for (int j = 0; j < 4; j++) {
                        FMA2(acc[j][2 * p],     a[j], w.x);
                        FMA2(acc[j][2 * p + 1], a[j], w.y);
                    }
                }
            }
        }
    }

    // epilogue: store h + accumulate per-channel sum / sumsq
    float p1[32], p2[32];
#pragma unroll
    for (int c = 0; c < 32; c++) { p1[c] = 0.f; p2[c] = 0.f; }
#pragma unroll
    for (int j = 0; j < 4; j++) {
        float hv[32];
#pragma unroll
        for (int p = 0; p < 16; p++) {
            unsigned u0, u1;
            UNPACK2(u0, u1, acc[j][p]);
            hv[2 * p]     = __uint_as_float(u0);
            hv[2 * p + 1] = __uint_as_float(u1);
        }
        if (ok[j]) {
            float* dst = hout + (size_t)r[j] * CC + half * 32;
#pragma unroll
            for (int q = 0; q < 8; q++) {
                float4 v;
                v.x = hv[4 * q]; v.y = hv[4 * q + 1];
                v.z = hv[4 * q + 2]; v.w = hv[4 * q + 3];
                *reinterpret_cast<float4*>(dst + q * 4) = v;
            }
#pragma unroll
            for (int c = 0; c < 32; c++) {
                p1[c] += hv[c];
                p2[c] += hv[c] * hv[c];
            }
        }
    }
    __syncthreads();
    float* red = Ws + half * 2048;
#pragma unroll
    for (int c = 0; c < 32; c++) {
        red[lane * 64 + c]      = p1[c];
        red[lane * 64 + 32 + c] = p2[c];
    }
    __syncwarp();
    float a = 0.f, b = 0.f;
#pragma unroll
    for (int k = 0; k < 32; k++) {
        a += red[k * 64 + lane];
        b += red[k * 64 + 32 + lane];
    }
    atomicAdd(&g_hsum[half * 32 + lane], a);
    atomicAdd(&g_hsq[half * 32 + lane], b);
}

// ---------------- K7: out = relu(a2*out + b2), in place (BN coeffs fused) ------
__global__ void __launch_bounds__(256) k7_epilogue(float* __restrict__ out,
                                                   const float* __restrict__ gamma,
                                                   const float* __restrict__ beta) {
    __shared__ float s_a[CC], s_b[CC];
    if (threadIdx.x < CC) {
        int c = threadIdx.x;
        float invN = 1.0f / (float)NN;
        float mean = g_hsum[c] * invN;
        float var = g_hsq[c] * invN - mean * mean;
        float a = gamma[c] * rsqrtf(var + BN_EPS);
        s_a[c] = a;
        s_b[c] = beta[c] - a * mean;
    }
    __syncthreads();
    int i = blockIdx.x * blockDim.x + threadIdx.x;
    int stride = gridDim.x * blockDim.x;
    float4* ov = reinterpret_cast<float4*>(out);
    for (int q = i; q < NN * 16; q += stride) {
        int c4 = (q & 15) * 4;
        float4 h = ov[q];
        float4 r;
        r.x = fmaxf(0.f, fmaf(s_a[c4 + 0], h.x, s_b[c4 + 0]));
        r.y = fmaxf(0.f, fmaf(s_a[c4 + 1], h.y, s_b[c4 + 1]));
        r.z = fmaxf(0.f, fmaf(s_a[c4 + 2], h.z, s_b[c4 + 2]));
        r.w = fmaxf(0.f, fmaf(s_a[c4 + 3], h.w, s_b[c4 + 3]));
        ov[q] = r;
    }
}

// ---------------- launch ---------------------------------------------------------
extern "C" void kernel_launch(void* const* d_in, const int* in_sizes, int n_in,
                              void* d_out, int out_size) {
    const float* x     = (const float*)d_in[0];
    const int*   ei    = (const int*)d_in[1];
    const float* ew    = (const float*)d_in[2];
    const float* pW    = (const float*)d_in[3];
    const float* pb    = (const float*)d_in[4];
    const float* pg    = (const float*)d_in[5];
    const float* pbeta = (const float*)d_in[6];
    const float* fW    = (const float*)d_in[7];
    const float* fb    = (const float*)d_in[8];
    const float* fg    = (const float*)d_in[9];
    const float* fbeta = (const float*)d_in[10];
    const float* coef  = (const float*)d_in[11];
    float* out = (float*)d_out;

    const int rowBlocks = (NN + 127) / 128;   // 391
    k0_zero<<<(NN + 255) / 256, 256>>>();
    k1_edge_stats<<<(EE + 255) / 256, 256>>>(ei, ew, coef);
    k2_xw<<<rowBlocks, 64>>>(x, pW);
    k4_scatter<<<1184, 256>>>(ei, ew, coef, pb, pg, pbeta);
    k5_final<<<rowBlocks, 64>>>(x, fW, fb, out);
    k7_epilogue<<<1024, 256>>>(out, fg, fbeta);
}

// round 9
// speedup vs baseline: 1.1970x; 1.1271x over previous
#include <cuda_runtime.h>
#include <cuda_fp16.h>

#define NN 50000
#define EE 800000
#define CC 64
#define BN_EPS 1e-5f

// ---------------- packed f32x2 helpers (Blackwell sm_103a) -------------------
#define PACK_DUP2(out, f) \
    asm("mov.b64 %0, {%1, %1};" : "=l"(out) : "r"(__float_as_uint(f)))
#define PACK2(out, f0, f1) \
    asm("mov.b64 %0, {%1, %2};" : "=l"(out) : "r"(__float_as_uint(f0)), "r"(__float_as_uint(f1)))
#define FMA2(d, a, b) \
    asm("fma.rn.f32x2 %0, %1, %2, %0;" : "+l"(d) : "l"(a), "l"(b))
#define UNPACK2(lo, hi, v) \
    asm("mov.b64 {%0, %1}, %2;" : "=r"(lo), "=r"(hi) : "l"(v))

// ---------------- scratch (static device arrays; no allocation) -------------
__device__ float2   g_cs[NN];        // (sum s, sum s^2) per src node
__device__ float    g_S1[CC];
__device__ float    g_S2[CC];
__device__ float    g_hsum[CC];
__device__ float    g_hsq[CC];
__device__ __half2  g_Yh[NN * 32];   // X @ pool_W, fp16x2 (k4 gather only)
__device__ float    g_aggf[NN * CC]; // scatter-max result (>= 0)

// ---------------- K0: zero small per-replay state -----------------------------
__global__ void k0_zero() {
    int i = blockIdx.x * blockDim.x + threadIdx.x;
    if (i < NN) g_cs[i] = make_float2(0.f, 0.f);
    if (i < CC) { g_S1[i] = 0.f; g_S2[i] = 0.f; g_hsum[i] = 0.f; g_hsq[i] = 0.f; }
}

// ---------------- K1: per-src sums of s, s^2 + zero agg ------------------------
__global__ void k1_edge_stats(const int* __restrict__ ei,
                              const float* __restrict__ ew,
                              const float* __restrict__ coefp) {
    int i = blockIdx.x * blockDim.x + threadIdx.x;
    int stride = gridDim.x * blockDim.x;
    // zero scatter-max target (safe: k1 atomics touch only g_cs; k4 runs later)
    float4 z = make_float4(0.f, 0.f, 0.f, 0.f);
    float4* a4 = reinterpret_cast<float4*>(g_aggf);
    for (int idx = i; idx < NN * CC / 4; idx += stride) a4[idx] = z;
    if (i >= EE) return;
    float coef = __ldg(coefp);
    int src = ei[i];
    float s = fmaf(coef, ew[i], 1.0f);
    atomicAdd(&g_cs[src].x, s);
    atomicAdd(&g_cs[src].y, s * s);
}

// ---------------- K2: Y = X @ pool_W (f32x2) + fused BN-stats, fp16 Y out -----
// 128 threads (4 warps). Warp w: column-half (w&1), row-group (w>>1).
// Thread handles 2 rows x 32 cols. Block covers 128 rows.
__global__ void __launch_bounds__(128) k2_xw(const float* __restrict__ x,
                                             const float* __restrict__ W) {
    __shared__ float Ws[8320];   // 4096 weights; 4x2080 conflict-free reduction
    {
        const float4* W4 = reinterpret_cast<const float4*>(W);
        float4* Ws4 = reinterpret_cast<float4*>(Ws);
        for (int i = threadIdx.x; i < CC * CC / 4; i += 128) Ws4[i] = W4[i];
    }
    __syncthreads();
    int wid  = threadIdx.x >> 5;
    int half = wid & 1;
    int grp  = wid >> 1;
    int lane = threadIdx.x & 31;
    int rbase = blockIdx.x * 128 + grp * 64 + lane;
    int r[2]; bool ok[2];
#pragma unroll
    for (int j = 0; j < 2; j++) { r[j] = rbase + 32 * j; ok[j] = r[j] < NN; }

    unsigned long long acc[2][16];
#pragma unroll
    for (int j = 0; j < 2; j++)
#pragma unroll
        for (int p = 0; p < 16; p++) acc[j][p] = 0ull;

    const float4 z4 = make_float4(0.f, 0.f, 0.f, 0.f);
#pragma unroll 4
    for (int k4 = 0; k4 < 16; k4++) {
        float4 xv[2];
#pragma unroll
        for (int j = 0; j < 2; j++)
            xv[j] = ok[j] ? *reinterpret_cast<const float4*>(
                                x + (size_t)r[j] * CC + k4 * 4)
                          : z4;
        float xk[2][4];
#pragma unroll
        for (int j = 0; j < 2; j++) {
            xk[j][0] = xv[j].x; xk[j][1] = xv[j].y;
            xk[j][2] = xv[j].z; xk[j][3] = xv[j].w;
        }
#pragma unroll
        for (int kk = 0; kk < 4; kk++) {
            unsigned long long a[2];
#pragma unroll
            for (int j = 0; j < 2; j++) PACK_DUP2(a[j], xk[j][kk]);
            const ulonglong2* wr = reinterpret_cast<const ulonglong2*>(
                &Ws[(k4 * 4 + kk) * CC + half * 32]);
#pragma unroll
            for (int p = 0; p < 8; p++) {
                ulonglong2 w = wr[p];
#pragma unroll
                for (int j = 0; j < 2; j++) {
                    FMA2(acc[j][2 * p],     a[j], w.x);
                    FMA2(acc[j][2 * p + 1], a[j], w.y);
                }
            }
        }
    }

    // epilogue: store Y (fp16) and accumulate BN-stat partials (fp32)
    float2 cs[2];
#pragma unroll
    for (int j = 0; j < 2; j++)
        cs[j] = ok[j] ? g_cs[r[j]] : make_float2(0.f, 0.f);
    float p1[32], p2[32];
#pragma unroll
    for (int c = 0; c < 32; c++) { p1[c] = 0.f; p2[c] = 0.f; }
#pragma unroll
    for (int j = 0; j < 2; j++) {
        float yv[32];
#pragma unroll
        for (int p = 0; p < 16; p++) {
            unsigned u0, u1;
            UNPACK2(u0, u1, acc[j][p]);
            yv[2 * p]     = __uint_as_float(u0);
            yv[2 * p + 1] = __uint_as_float(u1);
        }
        if (ok[j]) {
            __half2 hh[16];
#pragma unroll
            for (int c2 = 0; c2 < 16; c2++)
                hh[c2] = __floats2half2_rn(yv[2 * c2], yv[2 * c2 + 1]);
            uint4* dst = reinterpret_cast<uint4*>(g_Yh + (size_t)r[j] * 32 + half * 16);
            const uint4* srcv = reinterpret_cast<const uint4*>(hh);
#pragma unroll
            for (int q = 0; q < 4; q++) dst[q] = srcv[q];
        }
#pragma unroll
        for (int c = 0; c < 32; c++) {
            p1[c] += cs[j].x * yv[c];
            p2[c] += cs[j].y * yv[c] * yv[c];
        }
    }
    // conflict-free block reduction (stride 65)
    __syncthreads();
    float* red = Ws + wid * 2080;
#pragma unroll
    for (int c = 0; c < 32; c++) {
        red[lane * 65 + c]      = p1[c];
        red[lane * 65 + 32 + c] = p2[c];
    }
    __syncwarp();
    float a = 0.f, b = 0.f;
#pragma unroll
    for (int k = 0; k < 32; k++) {
        a += red[k * 65 + lane];
        b += red[k * 65 + 32 + lane];
    }
    atomicAdd(&g_S1[half * 32 + lane], a);
    atomicAdd(&g_S2[half * 32 + lane], b);
}

// ---------------- K4: filtered scatter-max (round-6 exact shape) ---------------
// Warp per 32-edge chunk, 2 channels/lane. Filter: plain-load current agg,
// atomicMax only if greater (safe: agg monotone non-decreasing from 0).
__global__ void __launch_bounds__(256) k4_scatter(const int* __restrict__ ei,
                                                  const float* __restrict__ ew,
                                                  const float* __restrict__ coefp,
                                                  const float* __restrict__ pb,
                                                  const float* __restrict__ gamma,
                                                  const float* __restrict__ beta) {
    __shared__ float s_al[CC], s_de[CC];
    if (threadIdx.x < CC) {
        int c = threadIdx.x;
        float invE = 1.0f / (float)EE;
        float bb = pb[c];
        float mean = g_S1[c] * invE + bb;
        float msq = (g_S2[c] + 2.f * bb * g_S1[c]) * invE + bb * bb;
        float var = msq - mean * mean;
        float alpha = gamma[c] * rsqrtf(var + BN_EPS);
        s_al[c] = alpha;
        s_de[c] = beta[c] + alpha * (bb - mean);
    }
    __syncthreads();
    float coef = __ldg(coefp);
    int lane = threadIdx.x & 31;
    int warp = (blockIdx.x * blockDim.x + threadIdx.x) >> 5;
    int nwarps = (gridDim.x * blockDim.x) >> 5;
    float al0 = s_al[2 * lane], al1 = s_al[2 * lane + 1];
    float de0 = s_de[2 * lane], de1 = s_de[2 * lane + 1];
    for (int base = warp * 32; base < EE; base += nwarps * 32) {
        int e = base + lane;
        int src = ei[e];
        int dst = ei[EE + e];
        float s = fmaf(coef, ew[e], 1.0f);
#pragma unroll 4
        for (int i = 0; i < 32; i++) {
            int   sI = __shfl_sync(0xffffffffu, src, i);
            int   dI = __shfl_sync(0xffffffffu, dst, i);
            float sS = __shfl_sync(0xffffffffu, s, i);
            __half2 yh = __ldg(g_Yh + (size_t)sI * 32 + lane);
            float2 yv = __half22float2(yh);
            float v0 = fmaf(al0 * sS, yv.x, de0);
            float v1 = fmaf(al1 * sS, yv.y, de1);
            float* arow = g_aggf + (size_t)dI * CC + 2 * lane;
            float2 cur = *reinterpret_cast<const float2*>(arow);
            unsigned* au = reinterpret_cast<unsigned*>(arow);
            if (v0 > cur.x) atomicMax(au,     __float_as_uint(v0));
            if (v1 > cur.y) atomicMax(au + 1, __float_as_uint(v1));
        }
    }
}

// ---------------- K5: h = [x, agg] @ final_W + b (f32x2) + fused h-stats -------
// 128 threads (4 warps), 2 rows/thread, float4 weight prologue.
__global__ void __launch_bounds__(128) k5_final(const float* __restrict__ x,
                                                const float* __restrict__ Wf,
                                                const float* __restrict__ fb,
                                                float* __restrict__ hout) {
    __shared__ float Ws[8320];   // 8192 weights; reused as 4x2080 reduction
    {
        const float4* W4 = reinterpret_cast<const float4*>(Wf);
        float4* Ws4 = reinterpret_cast<float4*>(Ws);
        for (int i = threadIdx.x; i < 2 * CC * CC / 4; i += 128) Ws4[i] = W4[i];
    }
    __syncthreads();
    int wid  = threadIdx.x >> 5;
    int half = wid & 1;
    int grp  = wid >> 1;
    int lane = threadIdx.x & 31;
    int rbase = blockIdx.x * 128 + grp * 64 + lane;
    int r[2]; bool ok[2];
#pragma unroll
    for (int j = 0; j < 2; j++) { r[j] = rbase + 32 * j; ok[j] = r[j] < NN; }

    unsigned long long acc[2][16];
    {
        const float* fbh = fb + half * 32;
        unsigned long long binit[16];
#pragma unroll
        for (int p = 0; p < 16; p++) PACK2(binit[p], fbh[2 * p], fbh[2 * p + 1]);
#pragma unroll
        for (int j = 0; j < 2; j++)
#pragma unroll
            for (int p = 0; p < 16; p++) acc[j][p] = binit[p];
    }

    const float4 z4 = make_float4(0.f, 0.f, 0.f, 0.f);
#pragma unroll
    for (int ph = 0; ph < 2; ph++) {
        const float* src = (ph == 0) ? x : g_aggf;
        const float* Wb  = Ws + ph * CC * CC;
#pragma unroll 4
        for (int k4 = 0; k4 < 16; k4++) {
            float4 xv[2];
#pragma unroll
            for (int j = 0; j < 2; j++)
                xv[j] = ok[j] ? *reinterpret_cast<const float4*>(
                                    src + (size_t)r[j] * CC + k4 * 4)
                              : z4;
            float xk[2][4];
#pragma unroll
            for (int j = 0; j < 2; j++) {
                xk[j][0] = xv[j].x; xk[j][1] = xv[j].y;
                xk[j][2] = xv[j].z; xk[j][3] = xv[j].w;
            }
#pragma unroll
            for (int kk = 0; kk < 4; kk++) {
                unsigned long long a[2];
#pragma unroll
                for (int j = 0; j < 2; j++) PACK_DUP2(a[j], xk[j][kk]);
                const ulonglong2* wr = reinterpret_cast<const ulonglong2*>(
                    &Wb[(k4 * 4 + kk) * CC + half * 32]);
#pragma unroll
                for (int p = 0; p < 8; p++) {
                    ulonglong2 w = wr[p];
#pragma unroll
                    for (int j = 0; j < 2; j++) {
                        FMA2(acc[j][2 * p],     a[j], w.x);
                        FMA2(acc[j][2 * p + 1], a[j], w.y);
                    }
                }
            }
        }
    }

    // epilogue: store h + accumulate per-channel sum / sumsq
    float p1[32], p2[32];
#pragma unroll
    for (int c = 0; c < 32; c++) { p1[c] = 0.f; p2[c] = 0.f; }
#pragma unroll
    for (int j = 0; j < 2; j++) {
        float hv[32];
#pragma unroll
        for (int p = 0; p < 16; p++) {
            unsigned u0, u1;
            UNPACK2(u0, u1, acc[j][p]);
            hv[2 * p]     = __uint_as_float(u0);
            hv[2 * p + 1] = __uint_as_float(u1);
        }
        if (ok[j]) {
            float* dst = hout + (size_t)r[j] * CC + half * 32;
#pragma unroll
            for (int q = 0; q < 8; q++) {
                float4 v;
                v.x = hv[4 * q]; v.y = hv[4 * q + 1];
                v.z = hv[4 * q + 2]; v.w = hv[4 * q + 3];
                *reinterpret_cast<float4*>(dst + q * 4) = v;
            }
#pragma unroll
            for (int c = 0; c < 32; c++) {
                p1[c] += hv[c];
                p2[c] += hv[c] * hv[c];
            }
        }
    }
    // conflict-free block reduction (stride 65)
    __syncthreads();
    float* red = Ws + wid * 2080;
#pragma unroll
    for (int c = 0; c < 32; c++) {
        red[lane * 65 + c]      = p1[c];
        red[lane * 65 + 32 + c] = p2[c];
    }
    __syncwarp();
    float a = 0.f, b = 0.f;
#pragma unroll
    for (int k = 0; k < 32; k++) {
        a += red[k * 65 + lane];
        b += red[k * 65 + 32 + lane];
    }
    atomicAdd(&g_hsum[half * 32 + lane], a);
    atomicAdd(&g_hsq[half * 32 + lane], b);
}

// ---------------- K7: out = relu(a2*out + b2), in place (BN coeffs fused) ------
__global__ void __launch_bounds__(256) k7_epilogue(float* __restrict__ out,
                                                   const float* __restrict__ gamma,
                                                   const float* __restrict__ beta) {
    __shared__ float s_a[CC], s_b[CC];
    if (threadIdx.x < CC) {
        int c = threadIdx.x;
        float invN = 1.0f / (float)NN;
        float mean = g_hsum[c] * invN;
        float var = g_hsq[c] * invN - mean * mean;
        float a = gamma[c] * rsqrtf(var + BN_EPS);
        s_a[c] = a;
        s_b[c] = beta[c] - a * mean;
    }
    __syncthreads();
    int i = blockIdx.x * blockDim.x + threadIdx.x;
    int stride = gridDim.x * blockDim.x;
    float4* ov = reinterpret_cast<float4*>(out);
    for (int q = i; q < NN * 16; q += stride) {
        int c4 = (q & 15) * 4;
        float4 h = ov[q];
        float4 r;
        r.x = fmaxf(0.f, fmaf(s_a[c4 + 0], h.x, s_b[c4 + 0]));
        r.y = fmaxf(0.f, fmaf(s_a[c4 + 1], h.y, s_b[c4 + 1]));
        r.z = fmaxf(0.f, fmaf(s_a[c4 + 2], h.z, s_b[c4 + 2]));
        r.w = fmaxf(0.f, fmaf(s_a[c4 + 3], h.w, s_b[c4 + 3]));
        ov[q] = r;
    }
}

// ---------------- launch ---------------------------------------------------------
extern "C" void kernel_launch(void* const* d_in, const int* in_sizes, int n_in,
                              void* d_out, int out_size) {
    const float* x     = (const float*)d_in[0];
    const int*   ei    = (const int*)d_in[1];
    const float* ew    = (const float*)d_in[2];
    const float* pW    = (const float*)d_in[3];
    const float* pb    = (const float*)d_in[4];
    const float* pg    = (const float*)d_in[5];
    const float* pbeta = (const float*)d_in[6];
    const float* fW    = (const float*)d_in[7];
    const float* fb    = (const float*)d_in[8];
    const float* fg    = (const float*)d_in[9];
    const float* fbeta = (const float*)d_in[10];
    const float* coef  = (const float*)d_in[11];
    float* out = (float*)d_out;

    const int rowBlocks = (NN + 127) / 128;   // 391
    k0_zero<<<(NN + 255) / 256, 256>>>();
    k1_edge_stats<<<(EE + 255) / 256, 256>>>(ei, ew, coef);
    k2_xw<<<rowBlocks, 128>>>(x, pW);
    k4_scatter<<<1184, 256>>>(ei, ew, coef, pb, pg, pbeta);
    k5_final<<<rowBlocks, 128>>>(x, fW, fb, out);
    k7_epilogue<<<1024, 256>>>(out, fg, fbeta);
}